// round 2
// baseline (speedup 1.0000x reference)
#include <cuda_runtime.h>
#include <cuda_bf16.h>
#include <cstdint>

// WeightedSumSessEmbedding: sparse COO [16384 x 1M] @ emb[1M x 64]
// NNZ=819200, row_idx sorted. Inputs: row_idx[i32], col_idx[i32],
// data[f32], num_ids[i32 scalar], embeddings[f32 1M*64]. Output f32 [16384*64].

#define EMB_DIM 64
#define CHUNK 128            // nnz per warp
#define THREADS 256          // 8 warps per block

__global__ void __launch_bounds__(THREADS, 8)
weighted_seg_sum_kernel(const int* __restrict__ row_idx,
                        const int* __restrict__ col_idx,
                        const float* __restrict__ data,
                        const float* __restrict__ emb,
                        float* __restrict__ out,
                        int nnz)
{
    const int warp = (blockIdx.x * blockDim.x + threadIdx.x) >> 5;
    const int lane = threadIdx.x & 31;

    const int start = warp * CHUNK;
    if (start >= nnz) return;
    const int end = min(start + CHUNK, nnz);

    // Each lane owns two consecutive dims via float2: [2*lane, 2*lane+1].
    const float2* __restrict__ emb2 = reinterpret_cast<const float2*>(emb);

    float2 acc = make_float2(0.0f, 0.0f);
    int cur_row = __ldg(&row_idx[start]);

    #define FLUSH()                                                          \
        do {                                                                 \
            float* o = out + (size_t)cur_row * EMB_DIM + 2 * lane;           \
            atomicAdd(o,     acc.x);                                         \
            atomicAdd(o + 1, acc.y);                                         \
            acc.x = 0.0f; acc.y = 0.0f;                                      \
        } while (0)

    #define STEP(r, w, e)                                                    \
        do {                                                                 \
            if ((r) != cur_row) { FLUSH(); cur_row = (r); }                  \
            acc.x = fmaf((w), (e).x, acc.x);                                 \
            acc.y = fmaf((w), (e).y, acc.y);                                 \
        } while (0)

    int i = start;
    // Unroll 8: issue all 8 independent 256B gathers (LDG.64 x 32 lanes)
    // before any consumer -> MLP = 8 per warp.
    for (; i + 8 <= end; i += 8) {
        const int4   ra = __ldg(reinterpret_cast<const int4*>(row_idx + i));
        const int4   rb = __ldg(reinterpret_cast<const int4*>(row_idx + i + 4));
        const int4   ca = __ldg(reinterpret_cast<const int4*>(col_idx + i));
        const int4   cb = __ldg(reinterpret_cast<const int4*>(col_idx + i + 4));
        const float4 wa = __ldg(reinterpret_cast<const float4*>(data + i));
        const float4 wb = __ldg(reinterpret_cast<const float4*>(data + i + 4));

        const float2 e0 = __ldg(emb2 + (size_t)ca.x * 32 + lane);
        const float2 e1 = __ldg(emb2 + (size_t)ca.y * 32 + lane);
        const float2 e2 = __ldg(emb2 + (size_t)ca.z * 32 + lane);
        const float2 e3 = __ldg(emb2 + (size_t)ca.w * 32 + lane);
        const float2 e4 = __ldg(emb2 + (size_t)cb.x * 32 + lane);
        const float2 e5 = __ldg(emb2 + (size_t)cb.y * 32 + lane);
        const float2 e6 = __ldg(emb2 + (size_t)cb.z * 32 + lane);
        const float2 e7 = __ldg(emb2 + (size_t)cb.w * 32 + lane);

        STEP(ra.x, wa.x, e0);
        STEP(ra.y, wa.y, e1);
        STEP(ra.z, wa.z, e2);
        STEP(ra.w, wa.w, e3);
        STEP(rb.x, wb.x, e4);
        STEP(rb.y, wb.y, e5);
        STEP(rb.z, wb.z, e6);
        STEP(rb.w, wb.w, e7);
    }
    // Scalar tail (nnz generally a multiple of 8; kept for safety).
    for (; i < end; ++i) {
        const int   r = __ldg(&row_idx[i]);
        const int   c = __ldg(&col_idx[i]);
        const float w = __ldg(&data[i]);
        const float2 e = __ldg(emb2 + (size_t)c * 32 + lane);
        STEP(r, w, e);
    }

    FLUSH();

    #undef STEP
    #undef FLUSH
}

extern "C" void kernel_launch(void* const* d_in, const int* in_sizes, int n_in,
                              void* d_out, int out_size)
{
    const int*   row_idx = (const int*)  d_in[0];
    const int*   col_idx = (const int*)  d_in[1];
    const float* data    = (const float*)d_in[2];
    const float* emb     = (const float*)d_in[4];
    float*       out     = (float*)d_out;

    const int nnz = in_sizes[0];

    cudaMemsetAsync(out, 0, (size_t)out_size * sizeof(float));

    const int warps  = (nnz + CHUNK - 1) / CHUNK;
    const int blocks = (warps * 32 + THREADS - 1) / THREADS;
    weighted_seg_sum_kernel<<<blocks, THREADS>>>(
        row_idx, col_idx, data, emb, out, nnz);
}

// round 3
// speedup vs baseline: 1.4389x; 1.4389x over previous
#include <cuda_runtime.h>
#include <cuda_bf16.h>
#include <cstdint>

// WeightedSumSessEmbedding: sparse COO [16384 x 1M] @ emb[1M x 64]
// NNZ=819200, row_idx sorted. Inputs: row_idx[i32], col_idx[i32],
// data[f32], num_ids[i32 scalar], embeddings[f32 1M*64]. Output f32 [16384*64].

#define EMB_DIM 64
#define CHUNK 64             // nnz per warp  -> 12800 warps total
#define THREADS 256          // 8 warps per block

__global__ void __launch_bounds__(THREADS, 5)   // ~51 regs: keep 8 gathers live
weighted_seg_sum_kernel(const int* __restrict__ row_idx,
                        const int* __restrict__ col_idx,
                        const float* __restrict__ data,
                        const float* __restrict__ emb,
                        float* __restrict__ out,
                        int nnz)
{
    const int warp = (blockIdx.x * blockDim.x + threadIdx.x) >> 5;
    const int lane = threadIdx.x & 31;

    const int start = warp * CHUNK;
    if (start >= nnz) return;
    const int end = min(start + CHUNK, nnz);

    // Each lane owns two consecutive dims via float2: [2*lane, 2*lane+1].
    const float2* __restrict__ emb2 = reinterpret_cast<const float2*>(emb);

    float2 acc = make_float2(0.0f, 0.0f);
    int cur_row = __ldg(&row_idx[start]);

    #define FLUSH()                                                          \
        do {                                                                 \
            float* o = out + (size_t)cur_row * EMB_DIM + 2 * lane;           \
            atomicAdd(o,     acc.x);                                         \
            atomicAdd(o + 1, acc.y);                                         \
            acc.x = 0.0f; acc.y = 0.0f;                                      \
        } while (0)

    #define STEP(r, w, e)                                                    \
        do {                                                                 \
            if ((r) != cur_row) { FLUSH(); cur_row = (r); }                  \
            acc.x = fmaf((w), (e).x, acc.x);                                 \
            acc.y = fmaf((w), (e).y, acc.y);                                 \
        } while (0)

    int i = start;
    // Unroll 8: all 8 independent 256B gathers issued before any consumer.
    for (; i + 8 <= end; i += 8) {
        const int4   ca = __ldg(reinterpret_cast<const int4*>(col_idx + i));
        const int4   cb = __ldg(reinterpret_cast<const int4*>(col_idx + i + 4));

        float2 e0 = __ldg(emb2 + (size_t)ca.x * 32 + lane);
        float2 e1 = __ldg(emb2 + (size_t)ca.y * 32 + lane);
        float2 e2 = __ldg(emb2 + (size_t)ca.z * 32 + lane);
        float2 e3 = __ldg(emb2 + (size_t)ca.w * 32 + lane);
        float2 e4 = __ldg(emb2 + (size_t)cb.x * 32 + lane);
        float2 e5 = __ldg(emb2 + (size_t)cb.y * 32 + lane);
        float2 e6 = __ldg(emb2 + (size_t)cb.z * 32 + lane);
        float2 e7 = __ldg(emb2 + (size_t)cb.w * 32 + lane);

        const int4   ra = __ldg(reinterpret_cast<const int4*>(row_idx + i));
        const int4   rb = __ldg(reinterpret_cast<const int4*>(row_idx + i + 4));
        const float4 wa = __ldg(reinterpret_cast<const float4*>(data + i));
        const float4 wb = __ldg(reinterpret_cast<const float4*>(data + i + 4));

        STEP(ra.x, wa.x, e0);
        STEP(ra.y, wa.y, e1);
        STEP(ra.z, wa.z, e2);
        STEP(ra.w, wa.w, e3);
        STEP(rb.x, wb.x, e4);
        STEP(rb.y, wb.y, e5);
        STEP(rb.z, wb.z, e6);
        STEP(rb.w, wb.w, e7);
    }
    // Tail (NNZ is a multiple of 8; kept for generality).
    for (; i < end; ++i) {
        const int   r = __ldg(&row_idx[i]);
        const int   c = __ldg(&col_idx[i]);
        const float w = __ldg(&data[i]);
        const float2 e = __ldg(emb2 + (size_t)c * 32 + lane);
        STEP(r, w, e);
    }

    FLUSH();

    #undef STEP
    #undef FLUSH
}

extern "C" void kernel_launch(void* const* d_in, const int* in_sizes, int n_in,
                              void* d_out, int out_size)
{
    const int*   row_idx = (const int*)  d_in[0];
    const int*   col_idx = (const int*)  d_in[1];
    const float* data    = (const float*)d_in[2];
    const float* emb     = (const float*)d_in[4];
    float*       out     = (float*)d_out;

    const int nnz = in_sizes[0];

    cudaMemsetAsync(out, 0, (size_t)out_size * sizeof(float));

    const int warps  = (nnz + CHUNK - 1) / CHUNK;
    const int blocks = (warps * 32 + THREADS - 1) / THREADS;
    weighted_seg_sum_kernel<<<blocks, THREADS>>>(
        row_idx, col_idx, data, emb, out, nnz);
}

// round 4
// speedup vs baseline: 1.5725x; 1.0929x over previous
#include <cuda_runtime.h>
#include <cuda_bf16.h>
#include <cstdint>

// WeightedSumSessEmbedding: sparse COO [16384 x 1M] @ emb[1M x 64]
// NNZ=819200, row_idx sorted. Inputs: row_idx[i32], col_idx[i32],
// data[f32], num_ids[i32 scalar], embeddings[f32 1M*64]. Output f32 [16384*64].

#define EMB_DIM 64
#define CHUNK 64             // nnz per warp  -> 12800 warps total
#define THREADS 256          // 8 warps per block
#define UNROLL 16

__global__ void __launch_bounds__(THREADS, 4)   // 64-reg budget: 16 gathers live
weighted_seg_sum_kernel(const int* __restrict__ row_idx,
                        const int* __restrict__ col_idx,
                        const float* __restrict__ data,
                        const float* __restrict__ emb,
                        float* __restrict__ out,
                        int nnz)
{
    const int warp = (blockIdx.x * blockDim.x + threadIdx.x) >> 5;
    const int lane = threadIdx.x & 31;

    const int start = warp * CHUNK;
    if (start >= nnz) return;
    const int end = min(start + CHUNK, nnz);

    // Each lane owns two consecutive dims via float2: [2*lane, 2*lane+1].
    const float2* __restrict__ emb2 = reinterpret_cast<const float2*>(emb);

    float2 acc = make_float2(0.0f, 0.0f);
    int cur_row = __ldg(&row_idx[start]);

    #define FLUSH()                                                          \
        do {                                                                 \
            float* o = out + (size_t)cur_row * EMB_DIM + 2 * lane;           \
            atomicAdd(o,     acc.x);                                         \
            atomicAdd(o + 1, acc.y);                                         \
            acc.x = 0.0f; acc.y = 0.0f;                                      \
        } while (0)

    #define STEP(r, w, e)                                                    \
        do {                                                                 \
            if ((r) != cur_row) { FLUSH(); cur_row = (r); }                  \
            acc.x = fmaf((w), (e).x, acc.x);                                 \
            acc.y = fmaf((w), (e).y, acc.y);                                 \
        } while (0)

    int i = start;
    // Unroll 16: all 16 independent 256B gathers issued before any consumer.
    for (; i + UNROLL <= end; i += UNROLL) {
        const int4 c0 = __ldg(reinterpret_cast<const int4*>(col_idx + i));
        const int4 c1 = __ldg(reinterpret_cast<const int4*>(col_idx + i + 4));
        const int4 c2 = __ldg(reinterpret_cast<const int4*>(col_idx + i + 8));
        const int4 c3 = __ldg(reinterpret_cast<const int4*>(col_idx + i + 12));
        const int cols[UNROLL] = {c0.x, c0.y, c0.z, c0.w,
                                  c1.x, c1.y, c1.z, c1.w,
                                  c2.x, c2.y, c2.z, c2.w,
                                  c3.x, c3.y, c3.z, c3.w};

        float2 e[UNROLL];
        #pragma unroll
        for (int j = 0; j < UNROLL; ++j)
            e[j] = __ldg(emb2 + (size_t)cols[j] * 32 + lane);

        const int4 r0 = __ldg(reinterpret_cast<const int4*>(row_idx + i));
        const int4 r1 = __ldg(reinterpret_cast<const int4*>(row_idx + i + 4));
        const int4 r2 = __ldg(reinterpret_cast<const int4*>(row_idx + i + 8));
        const int4 r3 = __ldg(reinterpret_cast<const int4*>(row_idx + i + 12));
        const float4 w0 = __ldg(reinterpret_cast<const float4*>(data + i));
        const float4 w1 = __ldg(reinterpret_cast<const float4*>(data + i + 4));
        const float4 w2 = __ldg(reinterpret_cast<const float4*>(data + i + 8));
        const float4 w3 = __ldg(reinterpret_cast<const float4*>(data + i + 12));
        const int rows[UNROLL] = {r0.x, r0.y, r0.z, r0.w,
                                  r1.x, r1.y, r1.z, r1.w,
                                  r2.x, r2.y, r2.z, r2.w,
                                  r3.x, r3.y, r3.z, r3.w};
        const float wts[UNROLL] = {w0.x, w0.y, w0.z, w0.w,
                                   w1.x, w1.y, w1.z, w1.w,
                                   w2.x, w2.y, w2.z, w2.w,
                                   w3.x, w3.y, w3.z, w3.w};

        #pragma unroll
        for (int j = 0; j < UNROLL; ++j)
            STEP(rows[j], wts[j], e[j]);
    }
    // Tail (NNZ is a multiple of 16; kept for generality).
    for (; i < end; ++i) {
        const int   r = __ldg(&row_idx[i]);
        const int   c = __ldg(&col_idx[i]);
        const float w = __ldg(&data[i]);
        const float2 e = __ldg(emb2 + (size_t)c * 32 + lane);
        STEP(r, w, e);
    }

    FLUSH();

    #undef STEP
    #undef FLUSH
}

extern "C" void kernel_launch(void* const* d_in, const int* in_sizes, int n_in,
                              void* d_out, int out_size)
{
    const int*   row_idx = (const int*)  d_in[0];
    const int*   col_idx = (const int*)  d_in[1];
    const float* data    = (const float*)d_in[2];
    const float* emb     = (const float*)d_in[4];
    float*       out     = (float*)d_out;

    const int nnz = in_sizes[0];

    cudaMemsetAsync(out, 0, (size_t)out_size * sizeof(float));

    const int warps  = (nnz + CHUNK - 1) / CHUNK;
    const int blocks = (warps * 32 + THREADS - 1) / THREADS;
    weighted_seg_sum_kernel<<<blocks, THREADS>>>(
        row_idx, col_idx, data, emb, out, nnz);
}